// round 1
// baseline (speedup 1.0000x reference)
#include <cuda_runtime.h>
#include <math.h>

// Problem constants (fixed by setup_inputs)
#define BATCH 8
#define HWPIX (512*512)        // 262144
#define NSEG  256
#define NFEAT 64
#define NACC  10               // count, sx0,sx1,sx2, m00,m01,m02,m11,m12,m22

// Scratch (no cudaMalloc allowed)
__device__ float g_acc[BATCH * NSEG * NACC];      // 20480 floats
__device__ float g_rn[BATCH * NSEG * NFEAT];      // 131072 floats

// ---------------------------------------------------------------------------
// Kernel 0: zero the accumulator
// ---------------------------------------------------------------------------
__global__ void zero_acc_kernel() {
    int i = blockIdx.x * blockDim.x + threadIdx.x;
    if (i < BATCH * NSEG * NACC) g_acc[i] = 0.0f;
}

// ---------------------------------------------------------------------------
// Kernel 1: per-pixel accumulate of (1, x, x x^T) into per-(batch,segment)
// shared-memory bins, flushed with global atomics.
// Grid: (32, BATCH), block: 256 threads. Each thread handles 8 float4 groups.
// ---------------------------------------------------------------------------
__device__ __forceinline__ void acc_pixel(float* sacc, int lab,
                                          float x0, float x1, float x2) {
    float* p = sacc + lab * NACC;
    atomicAdd(p + 0, 1.0f);
    atomicAdd(p + 1, x0);
    atomicAdd(p + 2, x1);
    atomicAdd(p + 3, x2);
    atomicAdd(p + 4, x0 * x0);
    atomicAdd(p + 5, x0 * x1);
    atomicAdd(p + 6, x0 * x2);
    atomicAdd(p + 7, x1 * x1);
    atomicAdd(p + 8, x1 * x2);
    atomicAdd(p + 9, x2 * x2);
}

__global__ void accum_kernel(const float* __restrict__ x,
                             const int* __restrict__ labels) {
    __shared__ float sacc[NSEG * NACC];   // 10 KB
    const int b = blockIdx.y;
    for (int i = threadIdx.x; i < NSEG * NACC; i += blockDim.x) sacc[i] = 0.0f;
    __syncthreads();

    const float4* __restrict__ xv = (const float4*)(x + (size_t)b * 3 * HWPIX);
    const int4*   __restrict__ lv = (const int4*)(labels + (size_t)b * HWPIX);
    // HW/4 = 65536 float4 groups per plane; 32 blocks -> 2048 groups/block;
    // 256 threads -> 8 groups/thread.
    const int base = blockIdx.x * 2048;

    #pragma unroll
    for (int it = 0; it < 8; it++) {
        const int g = base + threadIdx.x + it * 256;
        float4 a0 = xv[g];
        float4 a1 = xv[g + 65536];
        float4 a2 = xv[g + 131072];
        int4   l  = lv[g];
        acc_pixel(sacc, l.x, a0.x, a1.x, a2.x);
        acc_pixel(sacc, l.y, a0.y, a1.y, a2.y);
        acc_pixel(sacc, l.z, a0.z, a1.z, a2.z);
        acc_pixel(sacc, l.w, a0.w, a1.w, a2.w);
    }
    __syncthreads();

    float* gdst = g_acc + (size_t)b * NSEG * NACC;
    for (int i = threadIdx.x; i < NSEG * NACC; i += blockDim.x) {
        float v = sacc[i];
        if (v != 0.0f) atomicAdd(&gdst[i], v);
    }
}

// ---------------------------------------------------------------------------
// Kernel 2: per-segment stats -> combined[128] -> W_red matvec -> L2 normalize.
// 64 threads/block, each block processes 16 segments (grid = 128).
// W_red staged transposed in shared (padded stride 65 -> conflict-free).
// ---------------------------------------------------------------------------
#define SEGS_PER_BLOCK 16

__global__ void stats_kernel(const float* __restrict__ Wp,   // [64,3]
                             const float* __restrict__ bp,   // [64]
                             const float* __restrict__ Wr,   // [64,128]
                             const float* __restrict__ br) { // [64]
    __shared__ float sWr[128 * 65];   // transposed: sWr[g*65 + f]
    __shared__ float comb[2 * NFEAT];
    __shared__ float part[2];
    __shared__ float accs[NACC];

    const int f = threadIdx.x;   // 0..63

    // Stage W_red transposed: coalesced global read, conflict-free STS.
    for (int i = f; i < NFEAT * 128; i += NFEAT) {
        int row = i >> 7;     // f index
        int col = i & 127;    // g index
        sWr[col * 65 + row] = Wr[i];
    }
    const float w0 = Wp[f * 3 + 0];
    const float w1 = Wp[f * 3 + 1];
    const float w2 = Wp[f * 3 + 2];
    const float bb = bp[f];
    const float brf = br[f];
    __syncthreads();

    const int segBase = blockIdx.x * SEGS_PER_BLOCK;
    for (int si = 0; si < SEGS_PER_BLOCK; si++) {
        const int seg = segBase + si;
        if (f < NACC) accs[f] = g_acc[seg * NACC + f];
        __syncthreads();

        const float cnt = accs[0];
        const float cc  = fmaxf(cnt, 1.0f);
        const float sx0 = accs[1], sx1 = accs[2], sx2 = accs[3];
        const float m00 = accs[4], m01 = accs[5], m02 = accs[6];
        const float m11 = accs[7], m12 = accs[8], m22 = accs[9];

        const float wdot = w0 * sx0 + w1 * sx1 + w2 * sx2;
        const float ssum = wdot + cnt * bb;
        const float mean = ssum / cc;
        const float ssq  = w0 * w0 * m00 + w1 * w1 * m11 + w2 * w2 * m22
                         + 2.0f * (w0 * w1 * m01 + w0 * w2 * m02 + w1 * w2 * m12)
                         + 2.0f * bb * wdot + cnt * bb * bb;
        const float var = ssq / cc - mean * mean;
        const float sd  = sqrtf(fmaxf(var, 1e-6f));

        comb[f] = mean;
        comb[NFEAT + f] = sd;
        __syncthreads();

        float r = brf;
        #pragma unroll 16
        for (int g2 = 0; g2 < 128; g2++)
            r += sWr[g2 * 65 + f] * comb[g2];

        float sq = r * r;
        #pragma unroll
        for (int o = 16; o; o >>= 1)
            sq += __shfl_xor_sync(0xffffffffu, sq, o);
        if ((f & 31) == 0) part[f >> 5] = sq;
        __syncthreads();

        const float nrm = fmaxf(sqrtf(part[0] + part[1]), 1e-12f);
        g_rn[seg * NFEAT + f] = r / nrm;
        __syncthreads();   // protect accs/comb/part before next segment
    }
}

// ---------------------------------------------------------------------------
// Kernel 3: sim = rn @ rn^T per batch (256x256x64) + affine/BN/ReLU.
// Grid (4,4,BATCH), block (16,16). 64x64 output tile per block, 4x4 micro.
// ---------------------------------------------------------------------------
__global__ void sim_kernel(const float* __restrict__ ws,
                           const float* __restrict__ bs,
                           const float* __restrict__ gg,
                           const float* __restrict__ be,
                           const float* __restrict__ mu,
                           const float* __restrict__ va,
                           float* __restrict__ out) {
    __shared__ float As[64][NFEAT + 1];
    __shared__ float Bs[64][NFEAT + 1];

    const int b  = blockIdx.z;
    const int rb = blockIdx.y * 64;
    const int cb = blockIdx.x * 64;
    const float* __restrict__ rn = g_rn + (size_t)b * NSEG * NFEAT;

    const int t = threadIdx.y * 16 + threadIdx.x;
    for (int i = t; i < 64 * NFEAT; i += 256) {
        int r = i >> 6, k = i & 63;
        As[r][k] = rn[(rb + r) * NFEAT + k];
        Bs[r][k] = rn[(cb + r) * NFEAT + k];
    }
    __syncthreads();

    const int ty = threadIdx.y, tx = threadIdx.x;
    float acc[4][4];
    #pragma unroll
    for (int i = 0; i < 4; i++)
        #pragma unroll
        for (int j = 0; j < 4; j++) acc[i][j] = 0.0f;

    #pragma unroll 8
    for (int k = 0; k < NFEAT; k++) {
        float a[4], bv[4];
        #pragma unroll
        for (int i = 0; i < 4; i++) a[i]  = As[ty * 4 + i][k];
        #pragma unroll
        for (int j = 0; j < 4; j++) bv[j] = Bs[tx * 4 + j][k];
        #pragma unroll
        for (int i = 0; i < 4; i++)
            #pragma unroll
            for (int j = 0; j < 4; j++) acc[i][j] += a[i] * bv[j];
    }

    const float inv   = 1.0f / sqrtf(va[0] + 1e-5f);
    const float scale = ws[0] * gg[0] * inv;
    const float shift = gg[0] * (bs[0] - mu[0]) * inv + be[0];

    float* ob = out + (size_t)b * NSEG * NSEG;
    #pragma unroll
    for (int i = 0; i < 4; i++) {
        const int row = rb + ty * 4 + i;
        #pragma unroll
        for (int j = 0; j < 4; j++) {
            const int col = cb + tx * 4 + j;
            ob[row * NSEG + col] = fmaxf(scale * acc[i][j] + shift, 0.0f);
        }
    }
}

// ---------------------------------------------------------------------------
extern "C" void kernel_launch(void* const* d_in, const int* in_sizes, int n_in,
                              void* d_out, int out_size) {
    // Input order: x, labels, [num_spixels scalar], W_pix, b_pix, W_red, b_red,
    //              w_sim, b_sim, bn_gamma, bn_beta, bn_mean, bn_var
    const int off = (in_sizes[2] == 1) ? 1 : 0;   // num_spixels present?

    const float* x      = (const float*)d_in[0];
    const int*   labels = (const int*)d_in[1];
    const float* Wp = (const float*)d_in[2 + off];
    const float* bp = (const float*)d_in[3 + off];
    const float* Wr = (const float*)d_in[4 + off];
    const float* br = (const float*)d_in[5 + off];
    const float* ws = (const float*)d_in[6 + off];
    const float* bs = (const float*)d_in[7 + off];
    const float* gg = (const float*)d_in[8 + off];
    const float* be = (const float*)d_in[9 + off];
    const float* mu = (const float*)d_in[10 + off];
    const float* va = (const float*)d_in[11 + off];
    float* out = (float*)d_out;

    zero_acc_kernel<<<(BATCH * NSEG * NACC + 255) / 256, 256>>>();

    dim3 g1(32, BATCH);
    accum_kernel<<<g1, 256>>>(x, labels);

    stats_kernel<<<(BATCH * NSEG) / SEGS_PER_BLOCK, NFEAT>>>(Wp, bp, Wr, br);

    dim3 g3(4, 4, BATCH);
    sim_kernel<<<g3, dim3(16, 16)>>>(ws, bs, gg, be, mu, va, out);
}